// round 13
// baseline (speedup 1.0000x reference)
#include <cuda_runtime.h>
#include <math.h>

// Input order (metadata):
// 0: positions  [N*3] f32
// 1: cell       [9]   f32
// 2: sigma_tab  [NS*NS] f32
// 3: eps_tab    [NS*NS] f32
// 4: shift_tab  [NS*NS] f32
// 5: species    [N]   i32
// 6: pair_i     [P]   i32
// 7: pair_j     [P]   i32
// 8: shifts     [P*3] i32
// out: energy [N] f32
//
// FINAL — round-7 champion configuration.
//  - prep: pack (x,y,z,species) into one float4 table + zero output (4 atoms/thread).
//    One 16B 16-aligned gather per endpoint = exactly 1 L2 sector, species free.
//  - pair kernel: ILP=2, 256 threads/block, 32 regs, ~92% occupancy.
//    * 5 independent __ldcs (evict-streaming) loads issued back-to-back
//    * 2 random float4 gathers, default cache policy (measured faster than .cg)
//    * fused (sigma^6, 4*eps, shift_e) float4 smem table — one LDS per pair
//    * 2 global f32 atomicAdd (compile to RED, no return) per pair
//  Bound by LTS random-sector slots (~4.6/pair: 2 gathers + 2 REDs + stream);
//  measured ~91% LTS saturation — at the algorithmic floor for this access mix.

#define MAX_ATOMS 1048576
#define MAX_TAB   64
#define ILP       2

// packed (x, y, z, species-bits) per atom
__device__ float4 g_posw[MAX_ATOMS];

// fused prep: pack positions+species AND zero the output (4 atoms/thread)
__global__ void prep_kernel(const float* __restrict__ pos,
                            const int* __restrict__ species,
                            float* __restrict__ out, int n) {
    int base = (blockIdx.x * blockDim.x + threadIdx.x) * 4;
    if (base >= n) return;
    if (base + 4 <= n) {
        const float4* p4 = reinterpret_cast<const float4*>(pos + base * 3);
        float4 a = p4[0], b = p4[1], c = p4[2];
        int4 sp = *reinterpret_cast<const int4*>(species + base);
        g_posw[base + 0] = make_float4(a.x, a.y, a.z, __int_as_float(sp.x));
        g_posw[base + 1] = make_float4(a.w, b.x, b.y, __int_as_float(sp.y));
        g_posw[base + 2] = make_float4(b.z, b.w, c.x, __int_as_float(sp.z));
        g_posw[base + 3] = make_float4(c.y, c.z, c.w, __int_as_float(sp.w));
        *reinterpret_cast<float4*>(out + base) = make_float4(0.f, 0.f, 0.f, 0.f);
    } else {
        for (int i = base; i < n; i++) {
            g_posw[i] = make_float4(pos[3 * i], pos[3 * i + 1], pos[3 * i + 2],
                                    __int_as_float(species[i]));
            out[i] = 0.0f;
        }
    }
}

// shared body for one pair
__device__ __forceinline__ void lj_one_pair(
    int i, int j, float sfx, float sfy, float sfz,
    const float4* s_par, int ns, const float4& pwi, const float4& pwj,
    float* __restrict__ out) {
    float dx = pwj.x - pwi.x + sfx;
    float dy = pwj.y - pwi.y + sfy;
    float dz = pwj.z - pwi.z + sfz;

    int si = __float_as_int(pwi.w);
    int sj = __float_as_int(pwj.w);
    float4 par = s_par[si * ns + sj];

    float r2 = dx * dx + dy * dy + dz * dz;
    float r6 = r2 * r2 * r2;
    float sr6 = __fdividef(par.x, r6);
    float sr12 = sr6 * sr6;
    float e = par.y * (sr12 - sr6) - par.z;

    float half = 0.5f * e;
    atomicAdd(out + i, half);
    atomicAdd(out + j, half);
}

// main kernel: handles exactly Pmain = (P/ILP)*ILP pairs, no tail logic
__global__ __launch_bounds__(256)
void lj_pair_kernel(const float* __restrict__ cell,
                    const float* __restrict__ sigma_tab,
                    const float* __restrict__ eps_tab,
                    const float* __restrict__ shift_tab,
                    const int*   __restrict__ pair_i,
                    const int*   __restrict__ pair_j,
                    const int*   __restrict__ shifts,
                    float*       __restrict__ out,
                    int Pmain, int ns, int ns2) {
    __shared__ float4 s_par[MAX_TAB];
    if (threadIdx.x < ns2) {
        float sg = sigma_tab[threadIdx.x];
        float s3 = sg * sg * sg;
        s_par[threadIdx.x] = make_float4(s3 * s3, 4.0f * eps_tab[threadIdx.x],
                                         shift_tab[threadIdx.x], 0.0f);
    }
    __syncthreads();

    const float c00 = cell[0], c01 = cell[1], c02 = cell[2];
    const float c10 = cell[3], c11 = cell[4], c12 = cell[5];
    const float c20 = cell[6], c21 = cell[7], c22 = cell[8];

    const int base = (blockIdx.x * blockDim.x + threadIdx.x) * ILP;
    if (base >= Pmain) return;

    // all five streaming loads are independent — issue back-to-back
    // (touched once: evict-streaming hint)
    int2 vi = __ldcs(reinterpret_cast<const int2*>(pair_i + base));
    int2 vj = __ldcs(reinterpret_cast<const int2*>(pair_j + base));
    const int2* sv = reinterpret_cast<const int2*>(shifts + base * 3);
    int2 s0 = __ldcs(sv + 0);
    int2 s1 = __ldcs(sv + 1);
    int2 s2 = __ldcs(sv + 2);

    int ii[ILP] = {vi.x, vi.y};
    int jj[ILP] = {vj.x, vj.y};
    int ss[6]   = {s0.x, s0.y, s1.x, s1.y, s2.x, s2.y};

    // issue both random gathers up front (default cache policy)
    float4 pwi[ILP], pwj[ILP];
    #pragma unroll
    for (int k = 0; k < ILP; k++) {
        pwi[k] = g_posw[ii[k]];
        pwj[k] = g_posw[jj[k]];
    }

    #pragma unroll
    for (int k = 0; k < ILP; k++) {
        float fx = (float)ss[3 * k + 0];
        float fy = (float)ss[3 * k + 1];
        float fz = (float)ss[3 * k + 2];
        float sfx = fx * c00 + fy * c10 + fz * c20;
        float sfy = fx * c01 + fy * c11 + fz * c21;
        float sfz = fx * c02 + fy * c12 + fz * c22;
        lj_one_pair(ii[k], jj[k], sfx, sfy, sfz, s_par, ns, pwi[k], pwj[k], out);
    }
}

// remainder kernel: scalar, at most ILP-1 pairs (not launched when P % ILP == 0)
__global__ void lj_tail_kernel(const float* __restrict__ cell,
                               const float* __restrict__ sigma_tab,
                               const float* __restrict__ eps_tab,
                               const float* __restrict__ shift_tab,
                               const int*   __restrict__ pair_i,
                               const int*   __restrict__ pair_j,
                               const int*   __restrict__ shifts,
                               float*       __restrict__ out,
                               int Pstart, int P, int ns) {
    int p = Pstart + threadIdx.x;
    if (p >= P) return;

    int i = pair_i[p];
    int j = pair_j[p];
    float fx = (float)shifts[3 * p + 0];
    float fy = (float)shifts[3 * p + 1];
    float fz = (float)shifts[3 * p + 2];

    float sfx = fx * cell[0] + fy * cell[3] + fz * cell[6];
    float sfy = fx * cell[1] + fy * cell[4] + fz * cell[7];
    float sfz = fx * cell[2] + fy * cell[5] + fz * cell[8];

    float4 pwi = g_posw[i];
    float4 pwj = g_posw[j];

    float dx = pwj.x - pwi.x + sfx;
    float dy = pwj.y - pwi.y + sfy;
    float dz = pwj.z - pwi.z + sfz;

    int si = __float_as_int(pwi.w);
    int sj = __float_as_int(pwj.w);
    float sg  = sigma_tab[si * ns + sj];
    float s3  = sg * sg * sg;
    float s6  = s3 * s3;
    float eps = eps_tab[si * ns + sj];
    float sh  = shift_tab[si * ns + sj];

    float r2 = dx * dx + dy * dy + dz * dz;
    float r6 = r2 * r2 * r2;
    float sr6 = __fdividef(s6, r6);
    float sr12 = sr6 * sr6;
    float e = 4.0f * eps * (sr12 - sr6) - sh;

    float half = 0.5f * e;
    atomicAdd(out + i, half);
    atomicAdd(out + j, half);
}

extern "C" void kernel_launch(void* const* d_in, const int* in_sizes, int n_in,
                              void* d_out, int out_size) {
    const float* pos       = (const float*)d_in[0];
    const float* cell      = (const float*)d_in[1];
    const float* sigma_tab = (const float*)d_in[2];
    const float* eps_tab   = (const float*)d_in[3];
    const float* shift_tab = (const float*)d_in[4];
    const int*   species   = (const int*)d_in[5];
    const int*   pair_i    = (const int*)d_in[6];
    const int*   pair_j    = (const int*)d_in[7];
    const int*   shifts    = (const int*)d_in[8];
    float*       out       = (float*)d_out;

    int N = in_sizes[5];
    int P = in_sizes[6];
    int ns2 = in_sizes[2];
    int ns = 1;
    while (ns * ns < ns2) ns++;

    int pthreads = (N + 3) / 4;
    prep_kernel<<<(pthreads + 255) / 256, 256>>>(pos, species, out, N);

    int Pmain = (P / ILP) * ILP;
    int threads = Pmain / ILP;
    if (threads > 0) {
        lj_pair_kernel<<<(threads + 255) / 256, 256>>>(
            cell, sigma_tab, eps_tab, shift_tab,
            pair_i, pair_j, shifts, out, Pmain, ns, ns2);
    }
    if (Pmain < P) {
        lj_tail_kernel<<<1, ILP>>>(cell, sigma_tab, eps_tab, shift_tab,
                                   pair_i, pair_j, shifts, out, Pmain, P, ns);
    }
}

// round 14
// speedup vs baseline: 1.0267x; 1.0267x over previous
#include <cuda_runtime.h>
#include <math.h>

// Input order (metadata):
// 0: positions  [N*3] f32
// 1: cell       [9]   f32
// 2: sigma_tab  [NS*NS] f32
// 3: eps_tab    [NS*NS] f32
// 4: shift_tab  [NS*NS] f32
// 5: species    [N]   i32
// 6: pair_i     [P]   i32
// 7: pair_j     [P]   i32
// 8: shifts     [P*3] i32
// out: energy [N] f32
//
// Round-7 champion pair kernel + PDL overlap of the prep kernel:
// the pair kernel launches programmatically-early; its prologue (smem table,
// cell, 5 streaming loads) overlaps prep execution, and griddepcontrol.wait
// gates only the g_posw gathers / out atomics.

#define MAX_ATOMS 1048576
#define MAX_TAB   64
#define ILP       2

// packed (x, y, z, species-bits) per atom
__device__ float4 g_posw[MAX_ATOMS];

// fused prep: pack positions+species AND zero the output (4 atoms/thread)
__global__ void prep_kernel(const float* __restrict__ pos,
                            const int* __restrict__ species,
                            float* __restrict__ out, int n) {
    int base = (blockIdx.x * blockDim.x + threadIdx.x) * 4;
    if (base < n) {
        if (base + 4 <= n) {
            const float4* p4 = reinterpret_cast<const float4*>(pos + base * 3);
            float4 a = p4[0], b = p4[1], c = p4[2];
            int4 sp = *reinterpret_cast<const int4*>(species + base);
            g_posw[base + 0] = make_float4(a.x, a.y, a.z, __int_as_float(sp.x));
            g_posw[base + 1] = make_float4(a.w, b.x, b.y, __int_as_float(sp.y));
            g_posw[base + 2] = make_float4(b.z, b.w, c.x, __int_as_float(sp.z));
            g_posw[base + 3] = make_float4(c.y, c.z, c.w, __int_as_float(sp.w));
            *reinterpret_cast<float4*>(out + base) = make_float4(0.f, 0.f, 0.f, 0.f);
        } else {
            for (int i = base; i < n; i++) {
                g_posw[i] = make_float4(pos[3 * i], pos[3 * i + 1], pos[3 * i + 2],
                                        __int_as_float(species[i]));
                out[i] = 0.0f;
            }
        }
    }
}

// shared body for one pair
__device__ __forceinline__ void lj_one_pair(
    int i, int j, float sfx, float sfy, float sfz,
    const float4* s_par, int ns, const float4& pwi, const float4& pwj,
    float* __restrict__ out) {
    float dx = pwj.x - pwi.x + sfx;
    float dy = pwj.y - pwi.y + sfy;
    float dz = pwj.z - pwi.z + sfz;

    int si = __float_as_int(pwi.w);
    int sj = __float_as_int(pwj.w);
    float4 par = s_par[si * ns + sj];

    float r2 = dx * dx + dy * dy + dz * dz;
    float r6 = r2 * r2 * r2;
    float sr6 = __fdividef(par.x, r6);
    float sr12 = sr6 * sr6;
    float e = par.y * (sr12 - sr6) - par.z;

    float half = 0.5f * e;
    atomicAdd(out + i, half);
    atomicAdd(out + j, half);
}

// main kernel: handles exactly Pmain = (P/ILP)*ILP pairs, no tail logic.
// Launched with programmatic stream serialization: everything before the
// griddepcontrol.wait overlaps the prep kernel.
__global__ __launch_bounds__(256)
void lj_pair_kernel(const float* __restrict__ cell,
                    const float* __restrict__ sigma_tab,
                    const float* __restrict__ eps_tab,
                    const float* __restrict__ shift_tab,
                    const int*   __restrict__ pair_i,
                    const int*   __restrict__ pair_j,
                    const int*   __restrict__ shifts,
                    float*       __restrict__ out,
                    int Pmain, int ns, int ns2) {
    __shared__ float4 s_par[MAX_TAB];
    if (threadIdx.x < ns2) {
        float sg = sigma_tab[threadIdx.x];
        float s3 = sg * sg * sg;
        s_par[threadIdx.x] = make_float4(s3 * s3, 4.0f * eps_tab[threadIdx.x],
                                         shift_tab[threadIdx.x], 0.0f);
    }
    __syncthreads();

    const float c00 = cell[0], c01 = cell[1], c02 = cell[2];
    const float c10 = cell[3], c11 = cell[4], c12 = cell[5];
    const float c20 = cell[6], c21 = cell[7], c22 = cell[8];

    const int base = (blockIdx.x * blockDim.x + threadIdx.x) * ILP;
    if (base >= Pmain) {
        // still must pass the dependency gate before exiting (uniform not
        // required, but harmless) — no-op path
        asm volatile("griddepcontrol.wait;" ::: "memory");
        return;
    }

    // all five streaming loads are independent of prep's output —
    // issue back-to-back while prep may still be running
    int2 vi = __ldcs(reinterpret_cast<const int2*>(pair_i + base));
    int2 vj = __ldcs(reinterpret_cast<const int2*>(pair_j + base));
    const int2* sv = reinterpret_cast<const int2*>(shifts + base * 3);
    int2 s0 = __ldcs(sv + 0);
    int2 s1 = __ldcs(sv + 1);
    int2 s2 = __ldcs(sv + 2);

    int ii[ILP] = {vi.x, vi.y};
    int jj[ILP] = {vj.x, vj.y};
    int ss[6]   = {s0.x, s0.y, s1.x, s1.y, s2.x, s2.y};

    // gate: g_posw and zeroed out must be visible from here on
    asm volatile("griddepcontrol.wait;" ::: "memory");

    // issue both random gathers up front (default cache policy)
    float4 pwi[ILP], pwj[ILP];
    #pragma unroll
    for (int k = 0; k < ILP; k++) {
        pwi[k] = g_posw[ii[k]];
        pwj[k] = g_posw[jj[k]];
    }

    #pragma unroll
    for (int k = 0; k < ILP; k++) {
        float fx = (float)ss[3 * k + 0];
        float fy = (float)ss[3 * k + 1];
        float fz = (float)ss[3 * k + 2];
        float sfx = fx * c00 + fy * c10 + fz * c20;
        float sfy = fx * c01 + fy * c11 + fz * c21;
        float sfz = fx * c02 + fy * c12 + fz * c22;
        lj_one_pair(ii[k], jj[k], sfx, sfy, sfz, s_par, ns, pwi[k], pwj[k], out);
    }
}

// remainder kernel: scalar, at most ILP-1 pairs (not launched when P % ILP == 0)
__global__ void lj_tail_kernel(const float* __restrict__ cell,
                               const float* __restrict__ sigma_tab,
                               const float* __restrict__ eps_tab,
                               const float* __restrict__ shift_tab,
                               const int*   __restrict__ pair_i,
                               const int*   __restrict__ pair_j,
                               const int*   __restrict__ shifts,
                               float*       __restrict__ out,
                               int Pstart, int P, int ns) {
    int p = Pstart + threadIdx.x;
    if (p >= P) return;

    int i = pair_i[p];
    int j = pair_j[p];
    float fx = (float)shifts[3 * p + 0];
    float fy = (float)shifts[3 * p + 1];
    float fz = (float)shifts[3 * p + 2];

    float sfx = fx * cell[0] + fy * cell[3] + fz * cell[6];
    float sfy = fx * cell[1] + fy * cell[4] + fz * cell[7];
    float sfz = fx * cell[2] + fy * cell[5] + fz * cell[8];

    float4 pwi = g_posw[i];
    float4 pwj = g_posw[j];

    float dx = pwj.x - pwi.x + sfx;
    float dy = pwj.y - pwi.y + sfy;
    float dz = pwj.z - pwi.z + sfz;

    int si = __float_as_int(pwi.w);
    int sj = __float_as_int(pwj.w);
    float sg  = sigma_tab[si * ns + sj];
    float s3  = sg * sg * sg;
    float s6  = s3 * s3;
    float eps = eps_tab[si * ns + sj];
    float sh  = shift_tab[si * ns + sj];

    float r2 = dx * dx + dy * dy + dz * dz;
    float r6 = r2 * r2 * r2;
    float sr6 = __fdividef(s6, r6);
    float sr12 = sr6 * sr6;
    float e = 4.0f * eps * (sr12 - sr6) - sh;

    float half = 0.5f * e;
    atomicAdd(out + i, half);
    atomicAdd(out + j, half);
}

extern "C" void kernel_launch(void* const* d_in, const int* in_sizes, int n_in,
                              void* d_out, int out_size) {
    const float* pos       = (const float*)d_in[0];
    const float* cell      = (const float*)d_in[1];
    const float* sigma_tab = (const float*)d_in[2];
    const float* eps_tab   = (const float*)d_in[3];
    const float* shift_tab = (const float*)d_in[4];
    const int*   species   = (const int*)d_in[5];
    const int*   pair_i    = (const int*)d_in[6];
    const int*   pair_j    = (const int*)d_in[7];
    const int*   shifts    = (const int*)d_in[8];
    float*       out       = (float*)d_out;

    int N = in_sizes[5];
    int P = in_sizes[6];
    int ns2 = in_sizes[2];
    int ns = 1;
    while (ns * ns < ns2) ns++;

    int pthreads = (N + 3) / 4;
    prep_kernel<<<(pthreads + 255) / 256, 256>>>(pos, species, out, N);

    int Pmain = (P / ILP) * ILP;
    int threads = Pmain / ILP;
    int Pns = ns, Pns2 = ns2;
    if (threads > 0) {
        // PDL launch: allow this kernel to start while prep is still running;
        // griddepcontrol.wait inside gates the dependent accesses.
        cudaLaunchConfig_t cfg = {};
        cfg.gridDim  = dim3((threads + 255) / 256, 1, 1);
        cfg.blockDim = dim3(256, 1, 1);
        cfg.dynamicSmemBytes = 0;
        cfg.stream = 0;  // legacy default stream (same as <<<>>> above)
        cudaLaunchAttribute attr[1];
        attr[0].id = cudaLaunchAttributeProgrammaticStreamSerialization;
        attr[0].val.programmaticStreamSerializationAllowed = 1;
        cfg.attrs = attr;
        cfg.numAttrs = 1;
        cudaLaunchKernelEx(&cfg, lj_pair_kernel,
                           cell, sigma_tab, eps_tab, shift_tab,
                           pair_i, pair_j, shifts, out, Pmain, Pns, Pns2);
    }
    if (Pmain < P) {
        lj_tail_kernel<<<1, ILP>>>(cell, sigma_tab, eps_tab, shift_tab,
                                   pair_i, pair_j, shifts, out, Pmain, P, ns);
    }
}